// round 4
// baseline (speedup 1.0000x reference)
#include <cuda_runtime.h>
#include <math.h>

#define TT 256
#define DD 512
#define HH 256
#define EE 256
#define VV 8192
#define G3 768           // 3*H
#define DH (DD*HH)

// Scratch (static device globals; no runtime allocation).
__device__ float g_P[2][(size_t)VV * G3];   // precomputed emb@Wih^T + biases, [sel][v][3H]  (~50MB)
__device__ int   g_perm[TT * DD];           // per-step row permutation: edge=1 rows first (from 0), edge=0 from end
__device__ int   g_cnt1[TT];                // count of edge==1 rows per step
__device__ int   g_e_is_i32;                // edges dtype: 1 = int32, 0 = uint8

// ---------------------------------------------------------------------------
// Detect edges dtype. Values are 0/1. If stored as little-endian int32, bytes
// 4k+1..4k+3 are all zero across the first 256 elements; random 0/1 uint8 data
// passes that test with probability 2^-768 (never). Deterministic per input.
// ---------------------------------------------------------------------------
__global__ void detect_edges_kernel(const unsigned char* __restrict__ e) {
    int i32 = 1;
    for (int k = 0; k < 256; ++k) {
        if (e[4 * k + 1] | e[4 * k + 2] | e[4 * k + 3]) { i32 = 0; break; }
    }
    g_e_is_i32 = i32;
}

// ---------------------------------------------------------------------------
// Bucket rows by edge value per timestep. 1 block, 1 thread per t.
// ---------------------------------------------------------------------------
__global__ void bucket_kernel(const void* __restrict__ edges) {
    int t = threadIdx.x;
    if (t >= TT) return;
    const int is_i32 = g_e_is_i32;
    const unsigned char* e8  = (const unsigned char*)edges + (size_t)t * DD;
    const int*           e32 = (const int*)edges + (size_t)t * DD;
    int* p = g_perm + (size_t)t * DD;
    int i1 = 0, i0 = 0;
    for (int d = 0; d < DD; ++d) {
        bool ev = is_i32 ? (e32[d] != 0) : (e8[d] != 0);
        if (ev) p[i1++] = d;
        else    p[DD - 1 - (i0++)] = d;
    }
    g_cnt1[t] = i1;
}

// ---------------------------------------------------------------------------
// Precompute P[sel][v][j] = dot(emb[v], Wih[j]) + bih[j] + (j < 2H ? bhh[j] : 0)
// (bhh of r,z gates folds into the preactivation; bhh_n must stay separate
//  because n = tanh(in + r*(hn + bhh_n)).)
// GEMM: M=V, N=768, K=256. 64x64 tile, 256 threads, 4x4 microtile, Kc=32.
// ---------------------------------------------------------------------------
__global__ void precompute_P_kernel(
    const float* __restrict__ emb,
    const float* __restrict__ cWih, const float* __restrict__ cbih, const float* __restrict__ cbhh,
    const float* __restrict__ sWih, const float* __restrict__ sbih, const float* __restrict__ sbhh)
{
    int sel = blockIdx.z;                     // 0 = sibling, 1 = child
    const float* Wih = sel ? cWih : sWih;
    const float* bih = sel ? cbih : sbih;
    const float* bhh = sel ? cbhh : sbhh;
    float* P = g_P[sel];

    __shared__ __align__(16) float As[32][64];   // [k][m]
    __shared__ __align__(16) float Bs[32][64];   // [k][n]

    int vbase = blockIdx.y * 64;
    int jbase = blockIdx.x * 64;
    int tid  = threadIdx.x;
    int rowg = tid >> 4;    // 0..15 -> 4 rows each
    int colg = tid & 15;    // 0..15 -> 4 cols each

    float acc[4][4];
#pragma unroll
    for (int i = 0; i < 4; ++i)
#pragma unroll
        for (int j = 0; j < 4; ++j) acc[i][j] = 0.f;

    for (int kb = 0; kb < EE; kb += 32) {
#pragma unroll
        for (int i = 0; i < 2; ++i) {
            int lin = tid + i * 256;          // 0..511 : 64 rows x 8 float4
            int m  = lin >> 3;
            int k4 = (lin & 7) << 2;
            float4 v = *(const float4*)&emb[(size_t)(vbase + m) * EE + kb + k4];
            As[k4 + 0][m] = v.x; As[k4 + 1][m] = v.y; As[k4 + 2][m] = v.z; As[k4 + 3][m] = v.w;
            float4 w = *(const float4*)&Wih[(size_t)(jbase + m) * EE + kb + k4];
            Bs[k4 + 0][m] = w.x; Bs[k4 + 1][m] = w.y; Bs[k4 + 2][m] = w.z; Bs[k4 + 3][m] = w.w;
        }
        __syncthreads();
#pragma unroll 8
        for (int k = 0; k < 32; ++k) {
            float4 a = *(const float4*)&As[k][rowg * 4];
            float4 b = *(const float4*)&Bs[k][colg * 4];
            float av[4] = {a.x, a.y, a.z, a.w};
            float bv[4] = {b.x, b.y, b.z, b.w};
#pragma unroll
            for (int i = 0; i < 4; ++i)
#pragma unroll
                for (int j = 0; j < 4; ++j)
                    acc[i][j] = fmaf(av[i], bv[j], acc[i][j]);
        }
        __syncthreads();
    }

#pragma unroll
    for (int i = 0; i < 4; ++i) {
        int v = vbase + rowg * 4 + i;
#pragma unroll
        for (int j = 0; j < 4; ++j) {
            int jj = jbase + colg * 4 + j;
            float bias = bih[jj] + (jj < 2 * HH ? bhh[jj] : 0.f);
            P[(size_t)v * G3 + jj] = acc[i][j] + bias;
        }
    }
}

// ---------------------------------------------------------------------------
// One recurrent step. Grid: (8 unit-tiles of 32, 32 row slots: 16 per edge group).
// Block computes GH = h_prev[rows] @ Whh_sel^T for a 32-row x 32-unit x 3-gate
// tile (GEMM tile 32 x 96, K=256), then fuses GRU gates + output write.
// Rows are taken from g_perm so every row in a block shares the same edge value
// (partial boundary tiles are masked).
// ---------------------------------------------------------------------------
__global__ void step_kernel(int t,
    const float* __restrict__ h_prev,          // [D,H]
    float* __restrict__ h_out,                 // [D,H] (= outs[t])
    const int* __restrict__ nodes_t,           // [D]
    const float* __restrict__ cWhh, const float* __restrict__ cbhh,
    const float* __restrict__ sWhh, const float* __restrict__ sbhh)
{
    __shared__ __align__(16) float As[64][32];   // [k][m]
    __shared__ float Bs[64][96];                 // [k][c]  c = gate*32 + ui
    __shared__ float Cs[32][96];                 // epilogue staging [m][c]
    __shared__ int Rs[32];
    __shared__ int Ns[32];
    __shared__ unsigned char Vs[32];

    int cnt1 = g_cnt1[t];
    int u0   = blockIdx.x * 32;
    int slot = blockIdx.y;
    int grp, pbase;
    if (slot < 16) {                 // edge==1 group (child GRU), front-anchored
        grp = 1; pbase = slot * 32;
        if (pbase >= cnt1) return;
    } else {                          // edge==0 group (sibling GRU), end-anchored
        grp = 0; pbase = DD - (slot - 16 + 1) * 32;
        if (pbase + 32 <= cnt1) return;
    }
    const float* Whh = grp ? cWhh : sWhh;
    const float* bhh = grp ? cbhh : sbhh;
    const float* P   = g_P[grp];

    int tid = threadIdx.x;
    if (tid < 32) {
        int p = pbase + tid;
        bool v = grp ? (p < cnt1) : (p >= cnt1);
        int pp = v ? p : (grp ? 0 : DD - 1);       // clamp to a guaranteed-valid slot
        int d = g_perm[(size_t)t * DD + pp];
        Rs[tid] = d;
        Ns[tid] = nodes_t[d];
        Vs[tid] = v ? 1 : 0;
    }
    __syncthreads();

    int rowg = tid >> 5;   // 0..7  -> rows rowg*4 .. +3
    int colg = tid & 31;   // 0..31 -> cols colg*3 .. +2
    float acc[4][3];
#pragma unroll
    for (int i = 0; i < 4; ++i)
#pragma unroll
        for (int j = 0; j < 3; ++j) acc[i][j] = 0.f;

    for (int kb = 0; kb < HH; kb += 64) {
        // A tile: 32 rows x 64 k  (gathered rows, contiguous in k)
#pragma unroll
        for (int i = 0; i < 2; ++i) {
            int lin = tid + i * 256;        // 0..511 : 32 rows x 16 float4
            int m  = lin >> 4;
            int k4 = (lin & 15) << 2;
            float4 v = *(const float4*)&h_prev[(size_t)Rs[m] * HH + kb + k4];
            As[k4 + 0][m] = v.x; As[k4 + 1][m] = v.y; As[k4 + 2][m] = v.z; As[k4 + 3][m] = v.w;
        }
        // B tile: 96 weight rows x 64 k; col c -> Whh row (c/32)*256 + u0 + (c%32)
#pragma unroll
        for (int i = 0; i < 6; ++i) {
            int lin = tid + i * 256;        // 0..1535 : 96 cols x 16 float4
            int c  = lin >> 4;
            int k4 = (lin & 15) << 2;
            int wr = ((c >> 5) << 8) + u0 + (c & 31);
            float4 v = *(const float4*)&Whh[(size_t)wr * HH + kb + k4];
            Bs[k4 + 0][c] = v.x; Bs[k4 + 1][c] = v.y; Bs[k4 + 2][c] = v.z; Bs[k4 + 3][c] = v.w;
        }
        __syncthreads();
#pragma unroll 8
        for (int k = 0; k < 64; ++k) {
            float4 a = *(const float4*)&As[k][rowg * 4];
            float b0 = Bs[k][colg * 3 + 0];
            float b1 = Bs[k][colg * 3 + 1];
            float b2 = Bs[k][colg * 3 + 2];
            acc[0][0] = fmaf(a.x, b0, acc[0][0]);
            acc[0][1] = fmaf(a.x, b1, acc[0][1]);
            acc[0][2] = fmaf(a.x, b2, acc[0][2]);
            acc[1][0] = fmaf(a.y, b0, acc[1][0]);
            acc[1][1] = fmaf(a.y, b1, acc[1][1]);
            acc[1][2] = fmaf(a.y, b2, acc[1][2]);
            acc[2][0] = fmaf(a.z, b0, acc[2][0]);
            acc[2][1] = fmaf(a.z, b1, acc[2][1]);
            acc[2][2] = fmaf(a.z, b2, acc[2][2]);
            acc[3][0] = fmaf(a.w, b0, acc[3][0]);
            acc[3][1] = fmaf(a.w, b1, acc[3][1]);
            acc[3][2] = fmaf(a.w, b2, acc[3][2]);
        }
        __syncthreads();
    }

    // Stage C into smem for gate fusion ([m][c] so epilogue reads are conflict-free)
#pragma unroll
    for (int i = 0; i < 4; ++i)
#pragma unroll
        for (int j = 0; j < 3; ++j)
            Cs[rowg * 4 + i][colg * 3 + j] = acc[i][j];
    __syncthreads();

    // Gate fusion epilogue: 32 rows x 32 units = 1024 elements, 4 per thread
#pragma unroll
    for (int j = 0; j < 4; ++j) {
        int e  = tid + j * 256;
        int m  = e >> 5;
        int ui = e & 31;
        if (!Vs[m]) continue;
        int d = Rs[m];
        int u = u0 + ui;
        const float* Pp = P + (size_t)Ns[m] * G3;
        float gr = Pp[u];
        float gz = Pp[HH + u];
        float gn = Pp[2 * HH + u];
        float hr = Cs[m][ui];
        float hz = Cs[m][32 + ui];
        float hn = Cs[m][64 + ui] + bhh[2 * HH + u];
        float r = 1.f / (1.f + expf(-(gr + hr)));
        float z = 1.f / (1.f + expf(-(gz + hz)));
        float n = tanhf(gn + r * hn);
        float hp = h_prev[(size_t)d * HH + u];
        h_out[(size_t)d * HH + u] = (1.f - z) * n + z * hp;
    }
}

// ---------------------------------------------------------------------------
extern "C" void kernel_launch(void* const* d_in, const int* in_sizes, int n_in,
                              void* d_out, int out_size) {
    const int*           nodes = (const int*)d_in[0];
    const void*          edges = d_in[1];                 // bool: dtype detected on device
    const float*         h0    = (const float*)d_in[2];   // [1,D,H]
    const float*         emb   = (const float*)d_in[3];
    const float*         cWih  = (const float*)d_in[4];
    const float*         cWhh  = (const float*)d_in[5];
    const float*         cbih  = (const float*)d_in[6];
    const float*         cbhh  = (const float*)d_in[7];
    const float*         sWih  = (const float*)d_in[8];
    const float*         sWhh  = (const float*)d_in[9];
    const float*         sbih  = (const float*)d_in[10];
    const float*         sbhh  = (const float*)d_in[11];
    float* out = (float*)d_out;

    detect_edges_kernel<<<1, 1>>>((const unsigned char*)edges);
    bucket_kernel<<<1, 256>>>(edges);

    dim3 gP(G3 / 64, VV / 64, 2);     // 12 x 128 x 2
    precompute_P_kernel<<<gP, 256>>>(emb, cWih, cbih, cbhh, sWih, sbih, sbhh);

    dim3 gS(HH / 32, 32);             // 8 unit-tiles x 32 row slots
    const float* hp = h0;
    for (int t = 0; t < TT; ++t) {
        float* ho = out + (size_t)t * DH;
        step_kernel<<<gS, 256>>>(t, hp, ho, nodes + (size_t)t * DD,
                                 cWhh, cbhh, sWhh, sbhh);
        hp = ho;
    }

    // Final state h_final == outs[T-1]; harness output = [outs | h_final]
    cudaMemcpyAsync(out + (size_t)TT * DH, out + (size_t)(TT - 1) * DH,
                    (size_t)DH * sizeof(float), cudaMemcpyDeviceToDevice, 0);
}

// round 5
// speedup vs baseline: 2.1091x; 2.1091x over previous
#include <cuda_runtime.h>
#include <math.h>

#define TT 256
#define DD 512
#define HH 256
#define EE 256
#define VV 8192
#define G3 768           // 3*H
#define DH (DD*HH)
#define NB 136           // persistent blocks = 8 u-tiles x 17 slots

// Scratch (static device globals; no runtime allocation).
__device__ float g_P[2][(size_t)VV * G3];   // emb@Wih^T + biases, [sel][v][3H]
__device__ int   g_perm[TT * DD];
__device__ int   g_cnt1[TT];
__device__ int   g_e_is_i32;
__device__ unsigned int g_arrive = 0;       // grid barrier arrive counter (returns to 0 each barrier)
__device__ unsigned int g_epoch  = 0;       // grid barrier epoch (monotonic; compared relative)

// ---------------------------------------------------------------------------
__global__ void detect_edges_kernel(const unsigned char* __restrict__ e) {
    int i32 = 1;
    for (int k = 0; k < 256; ++k)
        if (e[4 * k + 1] | e[4 * k + 2] | e[4 * k + 3]) { i32 = 0; break; }
    g_e_is_i32 = i32;
}

__global__ void bucket_kernel(const void* __restrict__ edges) {
    int t = threadIdx.x;
    if (t >= TT) return;
    const int is_i32 = g_e_is_i32;
    const unsigned char* e8  = (const unsigned char*)edges + (size_t)t * DD;
    const int*           e32 = (const int*)edges + (size_t)t * DD;
    int* p = g_perm + (size_t)t * DD;
    int i1 = 0, i0 = 0;
    for (int d = 0; d < DD; ++d) {
        bool ev = is_i32 ? (e32[d] != 0) : (e8[d] != 0);
        if (ev) p[i1++] = d;
        else    p[DD - 1 - (i0++)] = d;
    }
    g_cnt1[t] = i1;
}

// ---------------------------------------------------------------------------
// P[sel][v][j] = dot(emb[v], Wih[j]) + bih[j] + (j < 2H ? bhh[j] : 0)
// ---------------------------------------------------------------------------
__global__ void precompute_P_kernel(
    const float* __restrict__ emb,
    const float* __restrict__ cWih, const float* __restrict__ cbih, const float* __restrict__ cbhh,
    const float* __restrict__ sWih, const float* __restrict__ sbih, const float* __restrict__ sbhh)
{
    int sel = blockIdx.z;
    const float* Wih = sel ? cWih : sWih;
    const float* bih = sel ? cbih : sbih;
    const float* bhh = sel ? cbhh : sbhh;
    float* P = g_P[sel];

    __shared__ __align__(16) float As[32][64];
    __shared__ __align__(16) float Bs[32][64];

    int vbase = blockIdx.y * 64;
    int jbase = blockIdx.x * 64;
    int tid  = threadIdx.x;
    int rowg = tid >> 4;
    int colg = tid & 15;

    float acc[4][4];
#pragma unroll
    for (int i = 0; i < 4; ++i)
#pragma unroll
        for (int j = 0; j < 4; ++j) acc[i][j] = 0.f;

    for (int kb = 0; kb < EE; kb += 32) {
#pragma unroll
        for (int i = 0; i < 2; ++i) {
            int lin = tid + i * 256;
            int m  = lin >> 3;
            int k4 = (lin & 7) << 2;
            float4 v = *(const float4*)&emb[(size_t)(vbase + m) * EE + kb + k4];
            As[k4 + 0][m] = v.x; As[k4 + 1][m] = v.y; As[k4 + 2][m] = v.z; As[k4 + 3][m] = v.w;
            float4 w = *(const float4*)&Wih[(size_t)(jbase + m) * EE + kb + k4];
            Bs[k4 + 0][m] = w.x; Bs[k4 + 1][m] = w.y; Bs[k4 + 2][m] = w.z; Bs[k4 + 3][m] = w.w;
        }
        __syncthreads();
#pragma unroll 8
        for (int k = 0; k < 32; ++k) {
            float4 a = *(const float4*)&As[k][rowg * 4];
            float4 b = *(const float4*)&Bs[k][colg * 4];
            float av[4] = {a.x, a.y, a.z, a.w};
            float bv[4] = {b.x, b.y, b.z, b.w};
#pragma unroll
            for (int i = 0; i < 4; ++i)
#pragma unroll
                for (int j = 0; j < 4; ++j)
                    acc[i][j] = fmaf(av[i], bv[j], acc[i][j]);
        }
        __syncthreads();
    }

#pragma unroll
    for (int i = 0; i < 4; ++i) {
        int v = vbase + rowg * 4 + i;
#pragma unroll
        for (int j = 0; j < 4; ++j) {
            int jj = jbase + colg * 4 + j;
            float bias = bih[jj] + (jj < 2 * HH ? bhh[jj] : 0.f);
            P[(size_t)v * G3 + jj] = acc[i][j] + bias;
        }
    }
}

// ---------------------------------------------------------------------------
// Persistent recurrent kernel. Grid: (8 u-tiles, 17 row slots) = 136 blocks,
// one per SM, co-resident. Each block keeps its Whh slice for BOTH GRUs in
// smem for the whole run (2 x 96 cols x 256 K = 192KB). Per step: gather 32
// h rows into smem, run barrier-free K=256 FFMA2 loop, fuse GRU epilogue,
// then grid-barrier.
// Dynamic smem: Bs 2*256*96 floats, then As 256*32 floats (Cs overlays As).
// ---------------------------------------------------------------------------
__device__ __forceinline__ unsigned long long dup2(float b) {
    unsigned long long r;
    asm("mov.b64 %0, {%1, %1};" : "=l"(r) : "r"(__float_as_uint(b)));
    return r;
}
__device__ __forceinline__ void fma2(unsigned long long& acc, unsigned long long a, unsigned long long b) {
    asm("fma.rn.f32x2 %0, %1, %2, %0;" : "+l"(acc) : "l"(a), "l"(b));
}
__device__ __forceinline__ float lo32(unsigned long long v) {
    unsigned int l, h; asm("mov.b64 {%0, %1}, %2;" : "=r"(l), "=r"(h) : "l"(v));
    return __uint_as_float(l);
}
__device__ __forceinline__ float hi32(unsigned long long v) {
    unsigned int l, h; asm("mov.b64 {%0, %1}, %2;" : "=r"(l), "=r"(h) : "l"(v));
    return __uint_as_float(h);
}

extern __shared__ float dyn_smem[];

__global__ void __launch_bounds__(256, 1) persistent_kernel(
    const float* __restrict__ h0,              // [D,H]
    float* __restrict__ out,                   // [T,D,H]
    const int* __restrict__ nodes,             // [T,D]
    const float* __restrict__ cWhh, const float* __restrict__ cbhh,
    const float* __restrict__ sWhh, const float* __restrict__ sbhh)
{
    float* sB = dyn_smem;                       // [2][256][96]
    float* sA = dyn_smem + 2 * 256 * 96;        // [256][32]; Cs [32][96] overlays
    float* sC = sA;

    __shared__ int Rs[32];
    __shared__ int Ns[32];
    __shared__ unsigned char Vs[32];
    __shared__ float s_bnb[2][32];              // bhh_n slice per group
    __shared__ unsigned int s_e0;

    int tid  = threadIdx.x;
    int u0   = blockIdx.x * 32;
    int slot = blockIdx.y;
    int rowg = tid >> 5;    // warp id: rows rowg*4..+3
    int colg = tid & 31;    // cols colg*3..+2

    // epoch base (safe: no block can advance epoch before this block arrives)
    if (tid == 0) s_e0 = *(volatile unsigned int*)&g_epoch;

    // ---- prologue: load both Whh slices into smem (once) ----
    for (int g = 0; g < 2; ++g) {
        const float* W = g ? cWhh : sWhh;
        for (int idx = tid; idx < 96 * 64; idx += 256) {   // 96 cols x 64 float4
            int c  = idx >> 6;
            int k4 = (idx & 63) << 2;
            int wr = ((c >> 5) << 8) + u0 + (c & 31);
            float4 v = *(const float4*)&W[(size_t)wr * HH + k4];
            float* b = sB + ((size_t)g * 256 + k4) * 96 + c;
            b[0 * 96] = v.x; b[1 * 96] = v.y; b[2 * 96] = v.z; b[3 * 96] = v.w;
        }
    }
    if (tid < 64) {
        int g = tid >> 5, ui = tid & 31;
        s_bnb[g][ui] = (g ? cbhh : sbhh)[2 * HH + u0 + ui];
    }
    __syncthreads();

    unsigned int e0 = s_e0;

    for (int t = 0; t < TT; ++t) {
        const float* h_prev = (t == 0) ? h0 : (out + (size_t)(t - 1) * DH);
        float*       h_out  = out + (size_t)t * DH;

        int cnt1 = g_cnt1[t];                   // broadcast L2 read
        int n1 = (cnt1 + 31) >> 5;
        int n0 = (DD - cnt1 + 31) >> 5;
        bool active; int grp = 0, pbase = 0;
        if (slot < n1)            { active = true;  grp = 1; pbase = slot * 32; }
        else if (slot < n1 + n0)  { active = true;  grp = 0; pbase = DD - (slot - n1 + 1) * 32; }
        else                       { active = false; }

        if (active) {
            if (tid < 32) {
                int p = pbase + tid;
                bool v = grp ? (p < cnt1) : (p >= cnt1);
                int pp = v ? p : (grp ? 0 : DD - 1);
                int d = g_perm[(size_t)t * DD + pp];
                Rs[tid] = d;
                Ns[tid] = nodes[(size_t)t * DD + d];
                Vs[tid] = v ? 1 : 0;
            }
            __syncthreads();

            // ---- gather A: 32 rows x 256 K into sA[k][m] ----
            {
                int m = tid & 31;
                int w = tid >> 5;               // k segment w*32..+31
                const float* hr = h_prev + (size_t)Rs[m] * HH + w * 32;
#pragma unroll
                for (int i = 0; i < 8; ++i) {
                    float4 v = *(const float4*)&hr[i * 4];
                    int k = w * 32 + i * 4;
                    sA[(k + 0) * 32 + m] = v.x;
                    sA[(k + 1) * 32 + m] = v.y;
                    sA[(k + 2) * 32 + m] = v.z;
                    sA[(k + 3) * 32 + m] = v.w;
                }
            }
            __syncthreads();

            // ---- K=256 packed-FMA loop (no barriers, no global traffic) ----
            const float* Bg = sB + (size_t)grp * (256 * 96) + colg * 3;
            unsigned long long acc0 = 0, acc1 = 0, acc2 = 0, acc3 = 0, acc4 = 0, acc5 = 0;
#pragma unroll 4
            for (int k = 0; k < HH; ++k) {
                ulonglong2 av = *(const ulonglong2*)(sA + k * 32 + rowg * 4);
                const float* b = Bg + k * 96;
                unsigned long long b0 = dup2(b[0]);
                unsigned long long b1 = dup2(b[1]);
                unsigned long long b2 = dup2(b[2]);
                fma2(acc0, av.x, b0); fma2(acc1, av.y, b0);
                fma2(acc2, av.x, b1); fma2(acc3, av.y, b1);
                fma2(acc4, av.x, b2); fma2(acc5, av.y, b2);
            }
            __syncthreads();     // all reads of sA done before Cs overlay

            // stage C [m][c]
            {
                float* c = sC + (size_t)(rowg * 4) * 96 + colg * 3;
                c[0 * 96 + 0] = lo32(acc0); c[1 * 96 + 0] = hi32(acc0);
                c[2 * 96 + 0] = lo32(acc1); c[3 * 96 + 0] = hi32(acc1);
                c[0 * 96 + 1] = lo32(acc2); c[1 * 96 + 1] = hi32(acc2);
                c[2 * 96 + 1] = lo32(acc3); c[3 * 96 + 1] = hi32(acc3);
                c[0 * 96 + 2] = lo32(acc4); c[1 * 96 + 2] = hi32(acc4);
                c[2 * 96 + 2] = lo32(acc5); c[3 * 96 + 2] = hi32(acc5);
            }
            __syncthreads();

            // ---- GRU gate epilogue: 32 rows x 32 units, 4 per thread ----
            const float* P = g_P[grp];
#pragma unroll
            for (int j = 0; j < 4; ++j) {
                int e  = tid + j * 256;
                int m  = e >> 5;
                int ui = e & 31;
                if (!Vs[m]) continue;
                int d = Rs[m];
                int u = u0 + ui;
                const float* Pp = P + (size_t)Ns[m] * G3;
                float gr = Pp[u];
                float gz = Pp[HH + u];
                float gn = Pp[2 * HH + u];
                float hr = sC[m * 96 + ui];
                float hz = sC[m * 96 + 32 + ui];
                float hn = sC[m * 96 + 64 + ui] + s_bnb[grp][ui];
                float r = 1.f / (1.f + __expf(-(gr + hr)));
                float z = 1.f / (1.f + __expf(-(gz + hz)));
                float n = tanhf(gn + r * hn);
                float hp = h_prev[(size_t)d * HH + u];
                h_out[(size_t)d * HH + u] = (1.f - z) * n + z * hp;
            }
        }

        // ---- grid barrier (skip after final step) ----
        if (t < TT - 1) {
            if (tid == 0) {
                __threadfence();
                unsigned int old = atomicAdd(&g_arrive, 1u);
                if (old == NB - 1) {
                    g_arrive = 0;
                    __threadfence();
                    atomicAdd(&g_epoch, 1u);
                } else {
                    while (((*(volatile unsigned int*)&g_epoch) - e0) < (unsigned int)(t + 1)) { }
                }
                __threadfence();
            }
            __syncthreads();
        }
    }
}

// ---------------------------------------------------------------------------
extern "C" void kernel_launch(void* const* d_in, const int* in_sizes, int n_in,
                              void* d_out, int out_size) {
    const int*           nodes = (const int*)d_in[0];
    const void*          edges = d_in[1];
    const float*         h0    = (const float*)d_in[2];
    const float*         emb   = (const float*)d_in[3];
    const float*         cWih  = (const float*)d_in[4];
    const float*         cWhh  = (const float*)d_in[5];
    const float*         cbih  = (const float*)d_in[6];
    const float*         cbhh  = (const float*)d_in[7];
    const float*         sWih  = (const float*)d_in[8];
    const float*         sWhh  = (const float*)d_in[9];
    const float*         sbih  = (const float*)d_in[10];
    const float*         sbhh  = (const float*)d_in[11];
    float* out = (float*)d_out;

    detect_edges_kernel<<<1, 1>>>((const unsigned char*)edges);
    bucket_kernel<<<1, 256>>>(edges);

    dim3 gP(G3 / 64, VV / 64, 2);
    precompute_P_kernel<<<gP, 256>>>(emb, cWih, cbih, cbhh, sWih, sbih, sbhh);

    static int smem_bytes = (2 * 256 * 96 + 256 * 32) * 4;   // 229376
    cudaFuncSetAttribute(persistent_kernel,
                         cudaFuncAttributeMaxDynamicSharedMemorySize, smem_bytes);
    persistent_kernel<<<dim3(8, 17), 256, smem_bytes>>>(
        h0, out, nodes, cWhh, cbhh, sWhh, sbhh);

    cudaMemcpyAsync(out + (size_t)TT * DH, out + (size_t)(TT - 1) * DH,
                    (size_t)DH * sizeof(float), cudaMemcpyDeviceToDevice, 0);
}

// round 6
// speedup vs baseline: 2.1989x; 1.0426x over previous
#include <cuda_runtime.h>
#include <math.h>

#define TT 256
#define DD 512
#define HH 256
#define EE 256
#define VV 8192
#define G3 768           // 3*H
#define DH (DD*HH)
#define NB 136           // persistent blocks = 8 u-tiles x 17 slots

// Scratch (static device globals; no runtime allocation).
__device__ float g_P[2][(size_t)VV * G3];   // emb@Wih^T + biases, [sel][v][3H]
__device__ int   g_perm[TT * DD];
__device__ int   g_cnt1[TT];
__device__ int   g_e_is_i32;
__device__ unsigned int g_arrive = 0;
__device__ unsigned int g_epoch  = 0;

// ---------------------------------------------------------------------------
__global__ void detect_edges_kernel(const unsigned char* __restrict__ e) {
    int i32 = 1;
    for (int k = 0; k < 256; ++k)
        if (e[4 * k + 1] | e[4 * k + 2] | e[4 * k + 3]) { i32 = 0; break; }
    g_e_is_i32 = i32;
}

__global__ void bucket_kernel(const void* __restrict__ edges) {
    int t = threadIdx.x;
    if (t >= TT) return;
    const int is_i32 = g_e_is_i32;
    const unsigned char* e8  = (const unsigned char*)edges + (size_t)t * DD;
    const int*           e32 = (const int*)edges + (size_t)t * DD;
    int* p = g_perm + (size_t)t * DD;
    int i1 = 0, i0 = 0;
    for (int d = 0; d < DD; ++d) {
        bool ev = is_i32 ? (e32[d] != 0) : (e8[d] != 0);
        if (ev) p[i1++] = d;
        else    p[DD - 1 - (i0++)] = d;
    }
    g_cnt1[t] = i1;
}

// ---------------------------------------------------------------------------
// P[sel][v][j] = dot(emb[v], Wih[j]) + bih[j] + (j < 2H ? bhh[j] : 0)
// ---------------------------------------------------------------------------
__global__ void precompute_P_kernel(
    const float* __restrict__ emb,
    const float* __restrict__ cWih, const float* __restrict__ cbih, const float* __restrict__ cbhh,
    const float* __restrict__ sWih, const float* __restrict__ sbih, const float* __restrict__ sbhh)
{
    int sel = blockIdx.z;
    const float* Wih = sel ? cWih : sWih;
    const float* bih = sel ? cbih : sbih;
    const float* bhh = sel ? cbhh : sbhh;
    float* P = g_P[sel];

    __shared__ __align__(16) float As[32][64];
    __shared__ __align__(16) float Bs[32][64];

    int vbase = blockIdx.y * 64;
    int jbase = blockIdx.x * 64;
    int tid  = threadIdx.x;
    int rowg = tid >> 4;
    int colg = tid & 15;

    float acc[4][4];
#pragma unroll
    for (int i = 0; i < 4; ++i)
#pragma unroll
        for (int j = 0; j < 4; ++j) acc[i][j] = 0.f;

    for (int kb = 0; kb < EE; kb += 32) {
#pragma unroll
        for (int i = 0; i < 2; ++i) {
            int lin = tid + i * 256;
            int m  = lin >> 3;
            int k4 = (lin & 7) << 2;
            float4 v = *(const float4*)&emb[(size_t)(vbase + m) * EE + kb + k4];
            As[k4 + 0][m] = v.x; As[k4 + 1][m] = v.y; As[k4 + 2][m] = v.z; As[k4 + 3][m] = v.w;
            float4 w = *(const float4*)&Wih[(size_t)(jbase + m) * EE + kb + k4];
            Bs[k4 + 0][m] = w.x; Bs[k4 + 1][m] = w.y; Bs[k4 + 2][m] = w.z; Bs[k4 + 3][m] = w.w;
        }
        __syncthreads();
#pragma unroll 8
        for (int k = 0; k < 32; ++k) {
            float4 a = *(const float4*)&As[k][rowg * 4];
            float4 b = *(const float4*)&Bs[k][colg * 4];
            float av[4] = {a.x, a.y, a.z, a.w};
            float bv[4] = {b.x, b.y, b.z, b.w};
#pragma unroll
            for (int i = 0; i < 4; ++i)
#pragma unroll
                for (int j = 0; j < 4; ++j)
                    acc[i][j] = fmaf(av[i], bv[j], acc[i][j]);
        }
        __syncthreads();
    }

#pragma unroll
    for (int i = 0; i < 4; ++i) {
        int v = vbase + rowg * 4 + i;
#pragma unroll
        for (int j = 0; j < 4; ++j) {
            int jj = jbase + colg * 4 + j;
            float bias = bih[jj] + (jj < 2 * HH ? bhh[jj] : 0.f);
            P[(size_t)v * G3 + jj] = acc[i][j] + bias;
        }
    }
}

// ---------------------------------------------------------------------------
// Packed f32x2 helpers
// ---------------------------------------------------------------------------
__device__ __forceinline__ unsigned long long dup2(float b) {
    unsigned long long r;
    asm("mov.b64 %0, {%1, %1};" : "=l"(r) : "r"(__float_as_uint(b)));
    return r;
}
__device__ __forceinline__ void fma2(unsigned long long& acc, unsigned long long a, unsigned long long b) {
    asm("fma.rn.f32x2 %0, %1, %2, %0;" : "+l"(acc) : "l"(a), "l"(b));
}
__device__ __forceinline__ void add2(unsigned long long& acc, unsigned long long o) {
    asm("add.rn.f32x2 %0, %0, %1;" : "+l"(acc) : "l"(o));
}

extern __shared__ float dyn_smem[];

// ---------------------------------------------------------------------------
// Persistent recurrent kernel, 512 threads, split-K x2.
// Grid (8 u-tiles, 17 slots) = 136 blocks, 1/SM. Whh slices (both GRUs) stay
// in smem all run. Per step: gather 32 h rows -> sA, each K-half (256 thr)
// runs a barrier-free K=128 FFMA2 loop on a 4-row x 3-col microtile, halves
// combine via add.rn.f32x2 through smem (overlay of sA), fused GRU epilogue,
// grid barrier.
// ---------------------------------------------------------------------------
__global__ void __launch_bounds__(512, 1) persistent_kernel(
    const float* __restrict__ h0,              // [D,H]
    float* __restrict__ out,                   // [T,D,H]
    const int* __restrict__ nodes,             // [T,D]
    const float* __restrict__ cWhh, const float* __restrict__ cbhh,
    const float* __restrict__ sWhh, const float* __restrict__ sbhh)
{
    float* sB = dyn_smem;                       // [2][256][96]
    float* sA = dyn_smem + 2 * 256 * 96;        // [256][32]; partial buf overlays
    unsigned long long* sPq = (unsigned long long*)sA;   // [256 threads][6]
    const float* sPf = (const float*)sA;

    __shared__ int Rs[32];
    __shared__ int Ns[32];
    __shared__ unsigned char Vs[32];
    __shared__ float s_bnb[2][32];
    __shared__ unsigned int s_e0;

    int tid   = threadIdx.x;
    int u0    = blockIdx.x * 32;
    int slot  = blockIdx.y;
    int half  = tid >> 8;          // K-half
    int htid  = tid & 255;
    int rowg  = htid >> 5;         // rows rowg*4..+3
    int colg  = htid & 31;         // cols colg*3..+2

    if (tid == 0) s_e0 = *(volatile unsigned int*)&g_epoch;

    // ---- prologue: load both Whh slices into smem (once) ----
    for (int g = 0; g < 2; ++g) {
        const float* W = g ? cWhh : sWhh;
        for (int idx = tid; idx < 96 * 64; idx += 512) {   // 96 cols x 64 float4
            int c  = idx >> 6;
            int k4 = (idx & 63) << 2;
            int wr = ((c >> 5) << 8) + u0 + (c & 31);
            float4 v = *(const float4*)&W[(size_t)wr * HH + k4];
            float* b = sB + ((size_t)g * 256 + k4) * 96 + c;
            b[0 * 96] = v.x; b[1 * 96] = v.y; b[2 * 96] = v.z; b[3 * 96] = v.w;
        }
    }
    if (tid < 64) {
        int g = tid >> 5, ui = tid & 31;
        s_bnb[g][ui] = (g ? cbhh : sbhh)[2 * HH + u0 + ui];
    }
    __syncthreads();

    unsigned int e0 = s_e0;

    for (int t = 0; t < TT; ++t) {
        const float* h_prev = (t == 0) ? h0 : (out + (size_t)(t - 1) * DH);
        float*       h_out  = out + (size_t)t * DH;

        int cnt1 = g_cnt1[t];
        int n1 = (cnt1 + 31) >> 5;
        int n0 = (DD - cnt1 + 31) >> 5;
        bool active; int grp = 0, pbase = 0;
        if (slot < n1)            { active = true;  grp = 1; pbase = slot * 32; }
        else if (slot < n1 + n0)  { active = true;  grp = 0; pbase = DD - (slot - n1 + 1) * 32; }
        else                       { active = false; }

        if (active) {
            if (tid < 32) {
                int p = pbase + tid;
                bool v = grp ? (p < cnt1) : (p >= cnt1);
                int pp = v ? p : (grp ? 0 : DD - 1);
                int d = g_perm[(size_t)t * DD + pp];
                Rs[tid] = d;
                Ns[tid] = nodes[(size_t)t * DD + d];
                Vs[tid] = v ? 1 : 0;
            }
            __syncthreads();

            // ---- gather A: 32 rows x 256 K into sA[k][m], 512 threads ----
#pragma unroll
            for (int i = 0; i < 4; ++i) {
                int lin = tid + i * 512;        // 0..2047 : 32 rows x 64 float4
                int m = lin >> 6;
                int k = (lin & 63) << 2;
                float4 v = *(const float4*)&h_prev[(size_t)Rs[m] * HH + k];
                sA[(k + 0) * 32 + m] = v.x;
                sA[(k + 1) * 32 + m] = v.y;
                sA[(k + 2) * 32 + m] = v.z;
                sA[(k + 3) * 32 + m] = v.w;
            }
            __syncthreads();

            // ---- split-K FFMA2 loop: this half does K=128 ----
            const float* Apt = sA + (half << 7) * 32 + rowg * 4;
            const float* Bpt = sB + (size_t)grp * (256 * 96) + (half << 7) * 96 + colg * 3;
            unsigned long long acc0 = 0, acc1 = 0, acc2 = 0, acc3 = 0, acc4 = 0, acc5 = 0;
#pragma unroll 8
            for (int k = 0; k < 128; ++k) {
                ulonglong2 av = *(const ulonglong2*)(Apt + k * 32);
                const float* b = Bpt + k * 96;
                unsigned long long b0 = dup2(b[0]);
                unsigned long long b1 = dup2(b[1]);
                unsigned long long b2 = dup2(b[2]);
                fma2(acc0, av.x, b0); fma2(acc1, av.y, b0);
                fma2(acc2, av.x, b1); fma2(acc3, av.y, b1);
                fma2(acc4, av.x, b2); fma2(acc5, av.y, b2);
            }
            __syncthreads();     // all sA reads done before partial-buffer overlay

            // ---- combine halves through smem ----
            if (half == 1) {
                int b = htid * 6;
                sPq[b + 0] = acc0; sPq[b + 1] = acc1; sPq[b + 2] = acc2;
                sPq[b + 3] = acc3; sPq[b + 4] = acc4; sPq[b + 5] = acc5;
            }
            __syncthreads();
            if (half == 0) {
                int b = htid * 6;
                add2(acc0, sPq[b + 0]); add2(acc1, sPq[b + 1]); add2(acc2, sPq[b + 2]);
                add2(acc3, sPq[b + 3]); add2(acc4, sPq[b + 4]); add2(acc5, sPq[b + 5]);
                sPq[b + 0] = acc0; sPq[b + 1] = acc1; sPq[b + 2] = acc2;
                sPq[b + 3] = acc3; sPq[b + 4] = acc4; sPq[b + 5] = acc5;
            }
            __syncthreads();

            // ---- GRU gate epilogue: 1024 elems, 2 per thread ----
            // C(m,c) lives at sPf[ ((th*6 + cj*2 + rp) << 1) + (m&1) ],
            // th = (m>>2)*32 + c/3, cj = c%3, rp = (m>>1)&1.
            const float* P = g_P[grp];
#pragma unroll
            for (int j = 0; j < 2; ++j) {
                int e  = tid + j * 512;
                int m  = e >> 5;
                int ui = e & 31;
                if (!Vs[m]) continue;
                int d = Rs[m];
                int u = u0 + ui;
                int rbase = ((m >> 2) << 5);
                int rp    = (m >> 1) & 1;
                int mlo   = m & 1;
                int c0 = ui,      g0 = c0 / 3, j0 = c0 - 3 * g0;
                int c1 = 32 + ui, g1 = c1 / 3, j1 = c1 - 3 * g1;
                int c2 = 64 + ui, g2 = c2 / 3, j2 = c2 - 3 * g2;
                float hr = sPf[(((rbase + g0) * 6 + j0 * 2 + rp) << 1) + mlo];
                float hz = sPf[(((rbase + g1) * 6 + j1 * 2 + rp) << 1) + mlo];
                float hn = sPf[(((rbase + g2) * 6 + j2 * 2 + rp) << 1) + mlo] + s_bnb[grp][ui];
                const float* Pp = P + (size_t)Ns[m] * G3;
                float gr = Pp[u];
                float gz = Pp[HH + u];
                float gn = Pp[2 * HH + u];
                float r = 1.f / (1.f + __expf(-(gr + hr)));
                float z = 1.f / (1.f + __expf(-(gz + hz)));
                float n = tanhf(gn + r * hn);
                float hp = h_prev[(size_t)d * HH + u];
                h_out[(size_t)d * HH + u] = (1.f - z) * n + z * hp;
            }
        }

        // ---- grid barrier (skip after final step) ----
        if (t < TT - 1) {
            if (tid == 0) {
                __threadfence();
                unsigned int old = atomicAdd(&g_arrive, 1u);
                if (old == NB - 1) {
                    g_arrive = 0;
                    __threadfence();
                    atomicAdd(&g_epoch, 1u);
                } else {
                    while (((*(volatile unsigned int*)&g_epoch) - e0) < (unsigned int)(t + 1)) { }
                }
                __threadfence();
            }
            __syncthreads();
        }
    }
}

// ---------------------------------------------------------------------------
extern "C" void kernel_launch(void* const* d_in, const int* in_sizes, int n_in,
                              void* d_out, int out_size) {
    const int*           nodes = (const int*)d_in[0];
    const void*          edges = d_in[1];
    const float*         h0    = (const float*)d_in[2];
    const float*         emb   = (const float*)d_in[3];
    const float*         cWih  = (const float*)d_in[4];
    const float*         cWhh  = (const float*)d_in[5];
    const float*         cbih  = (const float*)d_in[6];
    const float*         cbhh  = (const float*)d_in[7];
    const float*         sWih  = (const float*)d_in[8];
    const float*         sWhh  = (const float*)d_in[9];
    const float*         sbih  = (const float*)d_in[10];
    const float*         sbhh  = (const float*)d_in[11];
    float* out = (float*)d_out;

    detect_edges_kernel<<<1, 1>>>((const unsigned char*)edges);
    bucket_kernel<<<1, 256>>>(edges);

    dim3 gP(G3 / 64, VV / 64, 2);
    precompute_P_kernel<<<gP, 256>>>(emb, cWih, cbih, cbhh, sWih, sbih, sbhh);

    static int smem_bytes = (2 * 256 * 96 + 256 * 32) * 4;   // 229376
    cudaFuncSetAttribute(persistent_kernel,
                         cudaFuncAttributeMaxDynamicSharedMemorySize, smem_bytes);
    persistent_kernel<<<dim3(8, 17), 512, smem_bytes>>>(
        h0, out, nodes, cWhh, cbhh, sWhh, sbhh);

    cudaMemcpyAsync(out + (size_t)TT * DH, out + (size_t)(TT - 1) * DH,
                    (size_t)DH * sizeof(float), cudaMemcpyDeviceToDevice, 0);
}

// round 7
// speedup vs baseline: 2.4174x; 1.0993x over previous
#include <cuda_runtime.h>
#include <math.h>

#define TT 256
#define DD 512
#define HH 256
#define EE 256
#define VV 8192
#define G3 768           // 3*H
#define DH (DD*HH)
#define NB 136           // persistent blocks = 8 u-tiles x 17 slots

// Scratch (static device globals; no runtime allocation).
__device__ float g_P[2][(size_t)VV * G3];   // emb@Wih^T + biases, [sel][v][3H]
__device__ int   g_perm[TT * DD];
__device__ int   g_cnt1[TT];
__device__ int   g_e_is_i32;
__device__ unsigned int g_arrive = 0;
__device__ unsigned int g_epoch  = 0;

// ---------------------------------------------------------------------------
// Packed f32x2 helpers
// ---------------------------------------------------------------------------
__device__ __forceinline__ unsigned long long dup2(float b) {
    unsigned long long r;
    asm("mov.b64 %0, {%1, %1};" : "=l"(r) : "r"(__float_as_uint(b)));
    return r;
}
__device__ __forceinline__ void fma2(unsigned long long& acc, unsigned long long a, unsigned long long b) {
    asm("fma.rn.f32x2 %0, %1, %2, %0;" : "+l"(acc) : "l"(a), "l"(b));
}
__device__ __forceinline__ void add2(unsigned long long& acc, unsigned long long o) {
    asm("add.rn.f32x2 %0, %0, %1;" : "+l"(acc) : "l"(o));
}
__device__ __forceinline__ float lo32(unsigned long long v) {
    unsigned int l, h; asm("mov.b64 {%0, %1}, %2;" : "=r"(l), "=r"(h) : "l"(v));
    return __uint_as_float(l);
}
__device__ __forceinline__ float hi32(unsigned long long v) {
    unsigned int l, h; asm("mov.b64 {%0, %1}, %2;" : "=r"(l), "=r"(h) : "l"(v));
    return __uint_as_float(h);
}

// ---------------------------------------------------------------------------
__global__ void detect_edges_kernel(const unsigned char* __restrict__ e) {
    int i32 = 1;
    for (int k = 0; k < 256; ++k)
        if (e[4 * k + 1] | e[4 * k + 2] | e[4 * k + 3]) { i32 = 0; break; }
    g_e_is_i32 = i32;
}

__global__ void bucket_kernel(const void* __restrict__ edges) {
    int t = threadIdx.x;
    if (t >= TT) return;
    const int is_i32 = g_e_is_i32;
    const unsigned char* e8  = (const unsigned char*)edges + (size_t)t * DD;
    const int*           e32 = (const int*)edges + (size_t)t * DD;
    int* p = g_perm + (size_t)t * DD;
    int i1 = 0, i0 = 0;
    for (int d = 0; d < DD; ++d) {
        bool ev = is_i32 ? (e32[d] != 0) : (e8[d] != 0);
        if (ev) p[i1++] = d;
        else    p[DD - 1 - (i0++)] = d;
    }
    g_cnt1[t] = i1;
}

// ---------------------------------------------------------------------------
// P[sel][v][j] = dot(emb[v], Wih[j]) + bih[j] + (j < 2H ? bhh[j] : 0)
// 64x64 tile, 256 threads, 4x4 microtile with f32x2-packed row pairs.
// ---------------------------------------------------------------------------
__global__ void precompute_P_kernel(
    const float* __restrict__ emb,
    const float* __restrict__ cWih, const float* __restrict__ cbih, const float* __restrict__ cbhh,
    const float* __restrict__ sWih, const float* __restrict__ sbih, const float* __restrict__ sbhh)
{
    int sel = blockIdx.z;
    const float* Wih = sel ? cWih : sWih;
    const float* bih = sel ? cbih : sbih;
    const float* bhh = sel ? cbhh : sbhh;
    float* P = g_P[sel];

    __shared__ __align__(16) float As[32][64];
    __shared__ __align__(16) float Bs[32][64];

    int vbase = blockIdx.y * 64;
    int jbase = blockIdx.x * 64;
    int tid  = threadIdx.x;
    int rowg = tid >> 4;
    int colg = tid & 15;

    unsigned long long acc[2][4];   // row pairs (0,1),(2,3) x 4 cols
#pragma unroll
    for (int i = 0; i < 2; ++i)
#pragma unroll
        for (int j = 0; j < 4; ++j) acc[i][j] = 0ull;

    for (int kb = 0; kb < EE; kb += 32) {
#pragma unroll
        for (int i = 0; i < 2; ++i) {
            int lin = tid + i * 256;
            int m  = lin >> 3;
            int k4 = (lin & 7) << 2;
            float4 v = *(const float4*)&emb[(size_t)(vbase + m) * EE + kb + k4];
            As[k4 + 0][m] = v.x; As[k4 + 1][m] = v.y; As[k4 + 2][m] = v.z; As[k4 + 3][m] = v.w;
            float4 w = *(const float4*)&Wih[(size_t)(jbase + m) * EE + kb + k4];
            Bs[k4 + 0][m] = w.x; Bs[k4 + 1][m] = w.y; Bs[k4 + 2][m] = w.z; Bs[k4 + 3][m] = w.w;
        }
        __syncthreads();
#pragma unroll 8
        for (int k = 0; k < 32; ++k) {
            ulonglong2 av = *(const ulonglong2*)&As[k][rowg * 4];
            float4 b = *(const float4*)&Bs[k][colg * 4];
            unsigned long long b0 = dup2(b.x), b1 = dup2(b.y), b2 = dup2(b.z), b3 = dup2(b.w);
            fma2(acc[0][0], av.x, b0); fma2(acc[1][0], av.y, b0);
            fma2(acc[0][1], av.x, b1); fma2(acc[1][1], av.y, b1);
            fma2(acc[0][2], av.x, b2); fma2(acc[1][2], av.y, b2);
            fma2(acc[0][3], av.x, b3); fma2(acc[1][3], av.y, b3);
        }
        __syncthreads();
    }

#pragma unroll
    for (int i = 0; i < 2; ++i) {
        int v0 = vbase + rowg * 4 + i * 2;
#pragma unroll
        for (int j = 0; j < 4; ++j) {
            int jj = jbase + colg * 4 + j;
            float bias = bih[jj] + (jj < 2 * HH ? bhh[jj] : 0.f);
            P[(size_t)v0 * G3 + jj]       = lo32(acc[i][j]) + bias;
            P[(size_t)(v0 + 1) * G3 + jj] = hi32(acc[i][j]) + bias;
        }
    }
}

extern __shared__ float dyn_smem[];

// ---------------------------------------------------------------------------
// Persistent recurrent kernel, 512 threads, split-K x4, 8-row x 3-col microtile.
// Grid (8 u-tiles, 17 slots) = 136 blocks, 1/SM. Whh slices (both GRUs) stay
// in smem all run. Per step: prefetch epilogue operands (P rows, h_prev) into
// registers, gather 32 h rows -> sA, each K-quarter (128 thr) runs a
// barrier-free K=64 FFMA2 loop, quarters combine via add.rn.f32x2 through
// smem, q0 stages C, fused GRU epilogue, grid barrier.
// ---------------------------------------------------------------------------
__global__ void __launch_bounds__(512, 1) persistent_kernel(
    const float* __restrict__ h0,              // [D,H]
    float* __restrict__ out,                   // [T,D,H]
    const int* __restrict__ nodes,             // [T,D]
    const float* __restrict__ cWhh, const float* __restrict__ cbhh,
    const float* __restrict__ sWhh, const float* __restrict__ sbhh)
{
    float* sB = dyn_smem;                       // [2][256][96]
    float* sA = dyn_smem + 2 * 256 * 96;        // [256][32]; combine bufs + Cs overlay
    unsigned long long* sPq = (unsigned long long*)sA;
    float* sC = sA;                             // Cs [32][96] (12KB, == bufA region)

    __shared__ int Rs[32];
    __shared__ int Ns[32];
    __shared__ unsigned char Vs[32];
    __shared__ float s_bnb[2][32];
    __shared__ unsigned int s_e0;

    int tid   = threadIdx.x;
    int u0    = blockIdx.x * 32;
    int slot  = blockIdx.y;
    int q     = tid >> 7;          // K-quarter 0..3
    int qtid  = tid & 127;
    int rowg  = qtid >> 5;         // rows rowg*8..+7
    int colg  = qtid & 31;         // cols colg*3..+2

    if (tid == 0) s_e0 = *(volatile unsigned int*)&g_epoch;

    // ---- prologue: load both Whh slices into smem (once) ----
    for (int g = 0; g < 2; ++g) {
        const float* W = g ? cWhh : sWhh;
        for (int idx = tid; idx < 96 * 64; idx += 512) {   // 96 cols x 64 float4
            int c  = idx >> 6;
            int k4 = (idx & 63) << 2;
            int wr = ((c >> 5) << 8) + u0 + (c & 31);
            float4 v = *(const float4*)&W[(size_t)wr * HH + k4];
            float* b = sB + ((size_t)g * 256 + k4) * 96 + c;
            b[0 * 96] = v.x; b[1 * 96] = v.y; b[2 * 96] = v.z; b[3 * 96] = v.w;
        }
    }
    if (tid < 64) {
        int g = tid >> 5, ui = tid & 31;
        s_bnb[g][ui] = (g ? cbhh : sbhh)[2 * HH + u0 + ui];
    }
    __syncthreads();

    unsigned int e0 = s_e0;

    // epilogue element assignment (fixed): elems e = tid, tid+512
    int em0 = tid >> 5,          eu0 = tid & 31;
    int em1 = (tid + 512) >> 5,  eu1 = (tid + 512) & 31;

    for (int t = 0; t < TT; ++t) {
        const float* h_prev = (t == 0) ? h0 : (out + (size_t)(t - 1) * DH);
        float*       h_out  = out + (size_t)t * DH;

        int cnt1 = g_cnt1[t];
        int n1 = (cnt1 + 31) >> 5;
        int n0 = (DD - cnt1 + 31) >> 5;
        bool active; int grp = 0, pbase = 0;
        if (slot < n1)            { active = true;  grp = 1; pbase = slot * 32; }
        else if (slot < n1 + n0)  { active = true;  grp = 0; pbase = DD - (slot - n1 + 1) * 32; }
        else                       { active = false; }

        if (active) {
            if (tid < 32) {
                int p = pbase + tid;
                bool v = grp ? (p < cnt1) : (p >= cnt1);
                int pp = v ? p : (grp ? 0 : DD - 1);
                int d = g_perm[(size_t)t * DD + pp];
                Rs[tid] = d;
                Ns[tid] = nodes[(size_t)t * DD + d];
                Vs[tid] = v ? 1 : 0;
            }
            __syncthreads();

            // ---- prefetch epilogue operands (overlap with gather + k-loop) ----
            const float* P = g_P[grp];
            const float* Pp0 = P + (size_t)Ns[em0] * G3 + u0;
            const float* Pp1 = P + (size_t)Ns[em1] * G3 + u0;
            float pf_gr0 = __ldg(Pp0 + eu0);
            float pf_gz0 = __ldg(Pp0 + HH + eu0);
            float pf_gn0 = __ldg(Pp0 + 2 * HH + eu0);
            float pf_hp0 = __ldg(h_prev + (size_t)Rs[em0] * HH + u0 + eu0);
            float pf_gr1 = __ldg(Pp1 + eu1);
            float pf_gz1 = __ldg(Pp1 + HH + eu1);
            float pf_gn1 = __ldg(Pp1 + 2 * HH + eu1);
            float pf_hp1 = __ldg(h_prev + (size_t)Rs[em1] * HH + u0 + eu1);

            // ---- gather A: 32 rows x 256 K into sA[k][m], 512 threads ----
#pragma unroll
            for (int i = 0; i < 4; ++i) {
                int lin = tid + i * 512;        // 0..2047 : 32 rows x 64 float4
                int m = lin >> 6;
                int k = (lin & 63) << 2;
                float4 v = *(const float4*)&h_prev[(size_t)Rs[m] * HH + k];
                sA[(k + 0) * 32 + m] = v.x;
                sA[(k + 1) * 32 + m] = v.y;
                sA[(k + 2) * 32 + m] = v.z;
                sA[(k + 3) * 32 + m] = v.w;
            }
            __syncthreads();

            // ---- split-K x4 FFMA2 loop: this quarter does K=64 ----
            const float* Apt = sA + (q << 6) * 32 + rowg * 8;
            const float* Bpt = sB + (size_t)grp * (256 * 96) + (q << 6) * 96 + colg * 3;
            unsigned long long acc[3][4];   // [col][row-pair]
#pragma unroll
            for (int j = 0; j < 3; ++j)
#pragma unroll
                for (int p = 0; p < 4; ++p) acc[j][p] = 0ull;
#pragma unroll 8
            for (int k = 0; k < 64; ++k) {
                ulonglong2 a01 = *(const ulonglong2*)(Apt + k * 32);
                ulonglong2 a23 = *(const ulonglong2*)(Apt + k * 32 + 4);
                const float* b = Bpt + k * 96;
                unsigned long long b0 = dup2(b[0]);
                unsigned long long b1 = dup2(b[1]);
                unsigned long long b2 = dup2(b[2]);
                fma2(acc[0][0], a01.x, b0); fma2(acc[0][1], a01.y, b0);
                fma2(acc[0][2], a23.x, b0); fma2(acc[0][3], a23.y, b0);
                fma2(acc[1][0], a01.x, b1); fma2(acc[1][1], a01.y, b1);
                fma2(acc[1][2], a23.x, b1); fma2(acc[1][3], a23.y, b1);
                fma2(acc[2][0], a01.x, b2); fma2(acc[2][1], a01.y, b2);
                fma2(acc[2][2], a23.x, b2); fma2(acc[2][3], a23.y, b2);
            }
            __syncthreads();     // all sA reads done before combine-buffer overlay

            // ---- combine quarters: bufA = sPq[0..1535], bufB = sPq[1536..3071]
            unsigned long long* bufA = sPq;
            unsigned long long* bufB = sPq + 1536;
            if (q == 1) {
                unsigned long long* w = bufA + qtid * 12;
#pragma unroll
                for (int j = 0; j < 3; ++j)
#pragma unroll
                    for (int p = 0; p < 4; ++p) w[j * 4 + p] = acc[j][p];
            } else if (q == 3) {
                unsigned long long* w = bufB + qtid * 12;
#pragma unroll
                for (int j = 0; j < 3; ++j)
#pragma unroll
                    for (int p = 0; p < 4; ++p) w[j * 4 + p] = acc[j][p];
            }
            __syncthreads();
            if (q == 0) {
                const unsigned long long* r = bufA + qtid * 12;
#pragma unroll
                for (int j = 0; j < 3; ++j)
#pragma unroll
                    for (int p = 0; p < 4; ++p) add2(acc[j][p], r[j * 4 + p]);
            } else if (q == 2) {
                unsigned long long* rw = bufB + qtid * 12;
#pragma unroll
                for (int j = 0; j < 3; ++j)
#pragma unroll
                    for (int p = 0; p < 4; ++p) { add2(acc[j][p], rw[j * 4 + p]); rw[j * 4 + p] = acc[j][p]; }
            }
            __syncthreads();
            if (q == 0) {
                const unsigned long long* r = bufB + qtid * 12;
#pragma unroll
                for (int j = 0; j < 3; ++j)
#pragma unroll
                    for (int p = 0; p < 4; ++p) add2(acc[j][p], r[j * 4 + p]);
                // stage C [m][96]  (overlays bufA, which is dead now)
#pragma unroll
                for (int j = 0; j < 3; ++j)
#pragma unroll
                    for (int p = 0; p < 4; ++p) {
                        int r0 = rowg * 8 + p * 2;
                        sC[(size_t)r0 * 96 + colg * 3 + j]       = lo32(acc[j][p]);
                        sC[(size_t)(r0 + 1) * 96 + colg * 3 + j] = hi32(acc[j][p]);
                    }
            }
            __syncthreads();

            // ---- GRU gate epilogue: 1024 elems, 2 per thread, prefetched ----
            if (Vs[em0]) {
                float hr = sC[em0 * 96 + eu0];
                float hz = sC[em0 * 96 + 32 + eu0];
                float hn = sC[em0 * 96 + 64 + eu0] + s_bnb[grp][eu0];
                float r = 1.f / (1.f + __expf(-(pf_gr0 + hr)));
                float z = 1.f / (1.f + __expf(-(pf_gz0 + hz)));
                float n = tanhf(pf_gn0 + r * hn);
                h_out[(size_t)Rs[em0] * HH + u0 + eu0] = (1.f - z) * n + z * pf_hp0;
            }
            if (Vs[em1]) {
                float hr = sC[em1 * 96 + eu1];
                float hz = sC[em1 * 96 + 32 + eu1];
                float hn = sC[em1 * 96 + 64 + eu1] + s_bnb[grp][eu1];
                float r = 1.f / (1.f + __expf(-(pf_gr1 + hr)));
                float z = 1.f / (1.f + __expf(-(pf_gz1 + hz)));
                float n = tanhf(pf_gn1 + r * hn);
                h_out[(size_t)Rs[em1] * HH + u0 + eu1] = (1.f - z) * n + z * pf_hp1;
            }
        }

        // ---- grid barrier (skip after final step) ----
        if (t < TT - 1) {
            if (tid == 0) {
                __threadfence();
                unsigned int old = atomicAdd(&g_arrive, 1u);
                if (old == NB - 1) {
                    g_arrive = 0;
                    __threadfence();
                    atomicAdd(&g_epoch, 1u);
                } else {
                    while (((*(volatile unsigned int*)&g_epoch) - e0) < (unsigned int)(t + 1)) { }
                }
                __threadfence();
            }
            __syncthreads();
        }
    }
}

// ---------------------------------------------------------------------------
extern "C" void kernel_launch(void* const* d_in, const int* in_sizes, int n_in,
                              void* d_out, int out_size) {
    const int*           nodes = (const int*)d_in[0];
    const void*          edges = d_in[1];
    const float*         h0    = (const float*)d_in[2];
    const float*         emb   = (const float*)d_in[3];
    const float*         cWih  = (const float*)d_in[4];
    const float*         cWhh  = (const float*)d_in[5];
    const float*         cbih  = (const float*)d_in[6];
    const float*         cbhh  = (const float*)d_in[7];
    const float*         sWih  = (const float*)d_in[8];
    const float*         sWhh  = (const float*)d_in[9];
    const float*         sbih  = (const float*)d_in[10];
    const float*         sbhh  = (const float*)d_in[11];
    float* out = (float*)d_out;

    detect_edges_kernel<<<1, 1>>>((const unsigned char*)edges);
    bucket_kernel<<<1, 256>>>(edges);

    dim3 gP(G3 / 64, VV / 64, 2);
    precompute_P_kernel<<<gP, 256>>>(emb, cWih, cbih, cbhh, sWih, sbih, sbhh);

    static int smem_bytes = (2 * 256 * 96 + 256 * 32) * 4;   // 229376
    cudaFuncSetAttribute(persistent_kernel,
                         cudaFuncAttributeMaxDynamicSharedMemorySize, smem_bytes);
    persistent_kernel<<<dim3(8, 17), 512, smem_bytes>>>(
        h0, out, nodes, cWhh, cbhh, sWhh, sbhh);

    cudaMemcpyAsync(out + (size_t)TT * DH, out + (size_t)(TT - 1) * DH,
                    (size_t)DH * sizeof(float), cudaMemcpyDeviceToDevice, 0);
}

// round 8
// speedup vs baseline: 3.0218x; 1.2500x over previous
#include <cuda_runtime.h>
#include <math.h>

#define TT 256
#define DD 512
#define HH 256
#define EE 256
#define VV 8192
#define G3 768           // 3*H
#define DH (DD*HH)

// Scratch (static device globals; no runtime allocation).
__device__ float g_P[2][(size_t)VV * G3];   // emb@Wih^T + biases, [sel][v][3H]
__device__ int   g_perm[TT * DD];
__device__ int   g_cnt1[TT];
__device__ int   g_e_is_i32;
__device__ unsigned int g_arr8[8] = {0,0,0,0,0,0,0,0};  // per-column arrive
__device__ unsigned int g_arrive = 0;                    // top-level arrive
__device__ unsigned int g_epoch  = 0;                    // monotonic epoch

// ---------------------------------------------------------------------------
// Packed f32x2 helpers
// ---------------------------------------------------------------------------
__device__ __forceinline__ unsigned long long dup2(float b) {
    unsigned long long r;
    asm("mov.b64 %0, {%1, %1};" : "=l"(r) : "r"(__float_as_uint(b)));
    return r;
}
__device__ __forceinline__ void fma2(unsigned long long& acc, unsigned long long a, unsigned long long b) {
    asm("fma.rn.f32x2 %0, %1, %2, %0;" : "+l"(acc) : "l"(a), "l"(b));
}
__device__ __forceinline__ void add2(unsigned long long& acc, unsigned long long o) {
    asm("add.rn.f32x2 %0, %0, %1;" : "+l"(acc) : "l"(o));
}
__device__ __forceinline__ float lo32(unsigned long long v) {
    unsigned int l, h; asm("mov.b64 {%0, %1}, %2;" : "=r"(l), "=r"(h) : "l"(v));
    return __uint_as_float(l);
}
__device__ __forceinline__ float hi32(unsigned long long v) {
    unsigned int l, h; asm("mov.b64 {%0, %1}, %2;" : "=r"(l), "=r"(h) : "l"(v));
    return __uint_as_float(h);
}

// ---------------------------------------------------------------------------
__global__ void detect_edges_kernel(const unsigned char* __restrict__ e) {
    int i32 = 1;
    for (int k = 0; k < 256; ++k)
        if (e[4 * k + 1] | e[4 * k + 2] | e[4 * k + 3]) { i32 = 0; break; }
    g_e_is_i32 = i32;
}

__global__ void bucket_kernel(const void* __restrict__ edges) {
    int t = threadIdx.x;
    if (t >= TT) return;
    const int is_i32 = g_e_is_i32;
    const unsigned char* e8  = (const unsigned char*)edges + (size_t)t * DD;
    const int*           e32 = (const int*)edges + (size_t)t * DD;
    int* p = g_perm + (size_t)t * DD;
    int i1 = 0, i0 = 0;
    for (int d = 0; d < DD; ++d) {
        bool ev = is_i32 ? (e32[d] != 0) : (e8[d] != 0);
        if (ev) p[i1++] = d;
        else    p[DD - 1 - (i0++)] = d;
    }
    g_cnt1[t] = i1;
}

// ---------------------------------------------------------------------------
// P[sel][v][j] = dot(emb[v], Wih[j]) + bih[j] + (j < 2H ? bhh[j] : 0)
// 64x64 tile, 256 threads, 4x4 microtile with f32x2-packed row pairs.
// ---------------------------------------------------------------------------
__global__ void precompute_P_kernel(
    const float* __restrict__ emb,
    const float* __restrict__ cWih, const float* __restrict__ cbih, const float* __restrict__ cbhh,
    const float* __restrict__ sWih, const float* __restrict__ sbih, const float* __restrict__ sbhh)
{
    int sel = blockIdx.z;
    const float* Wih = sel ? cWih : sWih;
    const float* bih = sel ? cbih : sbih;
    const float* bhh = sel ? cbhh : sbhh;
    float* P = g_P[sel];

    __shared__ __align__(16) float As[32][64];
    __shared__ __align__(16) float Bs[32][64];

    int vbase = blockIdx.y * 64;
    int jbase = blockIdx.x * 64;
    int tid  = threadIdx.x;
    int rowg = tid >> 4;
    int colg = tid & 15;

    unsigned long long acc[2][4];
#pragma unroll
    for (int i = 0; i < 2; ++i)
#pragma unroll
        for (int j = 0; j < 4; ++j) acc[i][j] = 0ull;

    for (int kb = 0; kb < EE; kb += 32) {
#pragma unroll
        for (int i = 0; i < 2; ++i) {
            int lin = tid + i * 256;
            int m  = lin >> 3;
            int k4 = (lin & 7) << 2;
            float4 v = *(const float4*)&emb[(size_t)(vbase + m) * EE + kb + k4];
            As[k4 + 0][m] = v.x; As[k4 + 1][m] = v.y; As[k4 + 2][m] = v.z; As[k4 + 3][m] = v.w;
            float4 w = *(const float4*)&Wih[(size_t)(jbase + m) * EE + kb + k4];
            Bs[k4 + 0][m] = w.x; Bs[k4 + 1][m] = w.y; Bs[k4 + 2][m] = w.z; Bs[k4 + 3][m] = w.w;
        }
        __syncthreads();
#pragma unroll 8
        for (int k = 0; k < 32; ++k) {
            ulonglong2 av = *(const ulonglong2*)&As[k][rowg * 4];
            float4 b = *(const float4*)&Bs[k][colg * 4];
            unsigned long long b0 = dup2(b.x), b1 = dup2(b.y), b2 = dup2(b.z), b3 = dup2(b.w);
            fma2(acc[0][0], av.x, b0); fma2(acc[1][0], av.y, b0);
            fma2(acc[0][1], av.x, b1); fma2(acc[1][1], av.y, b1);
            fma2(acc[0][2], av.x, b2); fma2(acc[1][2], av.y, b2);
            fma2(acc[0][3], av.x, b3); fma2(acc[1][3], av.y, b3);
        }
        __syncthreads();
    }

#pragma unroll
    for (int i = 0; i < 2; ++i) {
        int v0 = vbase + rowg * 4 + i * 2;
#pragma unroll
        for (int j = 0; j < 4; ++j) {
            int jj = jbase + colg * 4 + j;
            float bias = bih[jj] + (jj < 2 * HH ? bhh[jj] : 0.f);
            P[(size_t)v0 * G3 + jj]       = lo32(acc[i][j]) + bias;
            P[(size_t)(v0 + 1) * G3 + jj] = hi32(acc[i][j]) + bias;
        }
    }
}

extern __shared__ float dyn_smem[];

// ---------------------------------------------------------------------------
// Persistent recurrent kernel, 512 threads, split-K x4, 8-row x 3-col microtile.
// sA uses a 4-row-block XOR swizzle (m ^ (k&28)) to cut gather STS conflicts
// from 32-way to 4-way while keeping k-loop A reads broadcast + 16B aligned.
// Two-level grid barrier (17-way per column, 8-way top).
// ---------------------------------------------------------------------------
__global__ void __launch_bounds__(512, 1) persistent_kernel(
    const float* __restrict__ h0,              // [D,H]
    float* __restrict__ out,                   // [T,D,H]
    const int* __restrict__ nodes,             // [T,D]
    const float* __restrict__ cWhh, const float* __restrict__ cbhh,
    const float* __restrict__ sWhh, const float* __restrict__ sbhh)
{
    float* sB = dyn_smem;                       // [2][256][96]
    float* sA = dyn_smem + 2 * 256 * 96;        // [256][32] swizzled; combine bufs + Cs overlay
    unsigned long long* sPq = (unsigned long long*)sA;
    float* sC = sA;                             // Cs [32][96] (12KB, overlays bufA)

    __shared__ int Rs[32];
    __shared__ int Ns[32];
    __shared__ unsigned char Vs[32];
    __shared__ float s_bnb[2][32];
    __shared__ unsigned int s_e0;

    int tid   = threadIdx.x;
    int u0    = blockIdx.x * 32;
    int slot  = blockIdx.y;
    int q     = tid >> 7;          // K-quarter 0..3
    int qtid  = tid & 127;
    int rowg  = qtid >> 5;         // rows rowg*8..+7
    int colg  = qtid & 31;         // cols colg*3..+2

    if (tid == 0) s_e0 = *(volatile unsigned int*)&g_epoch;

    // ---- prologue: load both Whh slices into smem (once) ----
    for (int g = 0; g < 2; ++g) {
        const float* W = g ? cWhh : sWhh;
        for (int idx = tid; idx < 96 * 64; idx += 512) {   // 96 cols x 64 float4
            int c  = idx >> 6;
            int k4 = (idx & 63) << 2;
            int wr = ((c >> 5) << 8) + u0 + (c & 31);
            float4 v = *(const float4*)&W[(size_t)wr * HH + k4];
            float* b = sB + ((size_t)g * 256 + k4) * 96 + c;
            b[0 * 96] = v.x; b[1 * 96] = v.y; b[2 * 96] = v.z; b[3 * 96] = v.w;
        }
    }
    if (tid < 64) {
        int g = tid >> 5, ui = tid & 31;
        s_bnb[g][ui] = (g ? cbhh : sbhh)[2 * HH + u0 + ui];
    }
    __syncthreads();

    unsigned int e0 = s_e0;

    // epilogue element assignment (fixed): elems e = tid, tid+512
    int em0 = tid >> 5,          eu0 = tid & 31;
    int em1 = (tid + 512) >> 5,  eu1 = (tid + 512) & 31;

    for (int t = 0; t < TT; ++t) {
        const float* h_prev = (t == 0) ? h0 : (out + (size_t)(t - 1) * DH);
        float*       h_out  = out + (size_t)t * DH;

        int cnt1 = g_cnt1[t];
        int n1 = (cnt1 + 31) >> 5;
        int n0 = (DD - cnt1 + 31) >> 5;
        bool active; int grp = 0, pbase = 0;
        if (slot < n1)            { active = true;  grp = 1; pbase = slot * 32; }
        else if (slot < n1 + n0)  { active = true;  grp = 0; pbase = DD - (slot - n1 + 1) * 32; }
        else                       { active = false; }

        if (active) {
            if (tid < 32) {
                int p = pbase + tid;
                bool v = grp ? (p < cnt1) : (p >= cnt1);
                int pp = v ? p : (grp ? 0 : DD - 1);
                int d = g_perm[(size_t)t * DD + pp];
                Rs[tid] = d;
                Ns[tid] = nodes[(size_t)t * DD + d];
                Vs[tid] = v ? 1 : 0;
            }
            __syncthreads();

            // ---- prefetch epilogue operands (overlap with gather + k-loop) ----
            const float* P = g_P[grp];
            const float* Pp0 = P + (size_t)Ns[em0] * G3 + u0;
            const float* Pp1 = P + (size_t)Ns[em1] * G3 + u0;
            float pf_gr0 = __ldg(Pp0 + eu0);
            float pf_gz0 = __ldg(Pp0 + HH + eu0);
            float pf_gn0 = __ldg(Pp0 + 2 * HH + eu0);
            float pf_hp0 = __ldg(h_prev + (size_t)Rs[em0] * HH + u0 + eu0);
            float pf_gr1 = __ldg(Pp1 + eu1);
            float pf_gz1 = __ldg(Pp1 + HH + eu1);
            float pf_gn1 = __ldg(Pp1 + 2 * HH + eu1);
            float pf_hp1 = __ldg(h_prev + (size_t)Rs[em1] * HH + u0 + eu1);

            // ---- gather A: 32 rows x 256 K into swizzled sA, 512 threads ----
            // layout: sA[k*32 + (m ^ (k&28))]; coalesced LDG, 4-way STS
#pragma unroll
            for (int i = 0; i < 4; ++i) {
                int lin = tid + i * 512;        // 0..2047 : 32 rows x 64 float4
                int m = lin >> 6;
                int k = (lin & 63) << 2;
                float4 v = *(const float4*)&h_prev[(size_t)Rs[m] * HH + k];
                int ms = m ^ (k & 28);          // k..k+3 share (k&28)
                sA[(k + 0) * 32 + ms] = v.x;
                sA[(k + 1) * 32 + ms] = v.y;
                sA[(k + 2) * 32 + ms] = v.z;
                sA[(k + 3) * 32 + ms] = v.w;
            }
            __syncthreads();

            // ---- split-K x4 FFMA2 loop: this quarter does K=64 ----
            const float* Apt = sA + (q << 6) * 32;
            const float* Bpt = sB + (size_t)grp * (256 * 96) + (q << 6) * 96 + colg * 3;
            int r8 = rowg * 8;
            unsigned long long acc[3][4];   // [col][row-pair]
#pragma unroll
            for (int j = 0; j < 3; ++j)
#pragma unroll
                for (int p = 0; p < 4; ++p) acc[j][p] = 0ull;
#pragma unroll 32
            for (int kk = 0; kk < 64; ++kk) {
                int sw = kk & 28;               // abs k = q*64+kk; (q*64)&28 == 0
                ulonglong2 a01 = *(const ulonglong2*)(Apt + kk * 32 + (r8 ^ sw));
                ulonglong2 a23 = *(const ulonglong2*)(Apt + kk * 32 + ((r8 + 4) ^ sw));
                const float* b = Bpt + kk * 96;
                unsigned long long b0 = dup2(b[0]);
                unsigned long long b1 = dup2(b[1]);
                unsigned long long b2 = dup2(b[2]);
                fma2(acc[0][0], a01.x, b0); fma2(acc[0][1], a01.y, b0);
                fma2(acc[0][2], a23.x, b0); fma2(acc[0][3], a23.y, b0);
                fma2(acc[1][0], a01.x, b1); fma2(acc[1][1], a01.y, b1);
                fma2(acc[1][2], a23.x, b1); fma2(acc[1][3], a23.y, b1);
                fma2(acc[2][0], a01.x, b2); fma2(acc[2][1], a01.y, b2);
                fma2(acc[2][2], a23.x, b2); fma2(acc[2][3], a23.y, b2);
            }
            __syncthreads();     // all sA reads done before combine-buffer overlay

            // ---- combine quarters (stride 13 u64 to dodge bank conflicts) ----
            unsigned long long* bufA = sPq;          // [128][13], 12 used
            unsigned long long* bufB = sPq + 1664;   // [128][13]
            if (q == 1) {
                unsigned long long* w = bufA + qtid * 13;
#pragma unroll
                for (int j = 0; j < 3; ++j)
#pragma unroll
                    for (int p = 0; p < 4; ++p) w[j * 4 + p] = acc[j][p];
            } else if (q == 3) {
                unsigned long long* w = bufB + qtid * 13;
#pragma unroll
                for (int j = 0; j < 3; ++j)
#pragma unroll
                    for (int p = 0; p < 4; ++p) w[j * 4 + p] = acc[j][p];
            }
            __syncthreads();
            if (q == 0) {
                const unsigned long long* r = bufA + qtid * 13;
#pragma unroll
                for (int j = 0; j < 3; ++j)
#pragma unroll
                    for (int p = 0; p < 4; ++p) add2(acc[j][p], r[j * 4 + p]);
            } else if (q == 2) {
                unsigned long long* rw = bufB + qtid * 13;
#pragma unroll
                for (int j = 0; j < 3; ++j)
#pragma unroll
                    for (int p = 0; p < 4; ++p) { add2(acc[j][p], rw[j * 4 + p]); rw[j * 4 + p] = acc[j][p]; }
            }
            __syncthreads();
            if (q == 0) {
                const unsigned long long* r = bufB + qtid * 13;
#pragma unroll
                for (int j = 0; j < 3; ++j)
#pragma unroll
                    for (int p = 0; p < 4; ++p) add2(acc[j][p], r[j * 4 + p]);
                // stage C [m][96]  (overlays bufA, dead; no overlap with bufB)
#pragma unroll
                for (int j = 0; j < 3; ++j)
#pragma unroll
                    for (int p = 0; p < 4; ++p) {
                        int r0 = rowg * 8 + p * 2;
                        sC[(size_t)r0 * 96 + colg * 3 + j]       = lo32(acc[j][p]);
                        sC[(size_t)(r0 + 1) * 96 + colg * 3 + j] = hi32(acc[j][p]);
                    }
            }
            __syncthreads();

            // ---- GRU gate epilogue: 1024 elems, 2 per thread, prefetched ----
            if (Vs[em0]) {
                float hr = sC[em0 * 96 + eu0];
                float hz = sC[em0 * 96 + 32 + eu0];
                float hn = sC[em0 * 96 + 64 + eu0] + s_bnb[grp][eu0];
                float r = 1.f / (1.f + __expf(-(pf_gr0 + hr)));
                float z = 1.f / (1.f + __expf(-(pf_gz0 + hz)));
                float n = tanhf(pf_gn0 + r * hn);
                h_out[(size_t)Rs[em0] * HH + u0 + eu0] = (1.f - z) * n + z * pf_hp0;
            }
            if (Vs[em1]) {
                float hr = sC[em1 * 96 + eu1];
                float hz = sC[em1 * 96 + 32 + eu1];
                float hn = sC[em1 * 96 + 64 + eu1] + s_bnb[grp][eu1];
                float r = 1.f / (1.f + __expf(-(pf_gr1 + hr)));
                float z = 1.f / (1.f + __expf(-(pf_gz1 + hz)));
                float n = tanhf(pf_gn1 + r * hn);
                h_out[(size_t)Rs[em1] * HH + u0 + eu1] = (1.f - z) * n + z * pf_hp1;
            }
        }

        // ---- two-level grid barrier (skip after final step) ----
        if (t < TT - 1) {
            if (tid == 0) {
                __threadfence();
                unsigned int o = atomicAdd(&g_arr8[blockIdx.x], 1u);
                if (o == 16) {                          // last of 17 in this column
                    g_arr8[blockIdx.x] = 0;
                    __threadfence();
                    unsigned int o2 = atomicAdd(&g_arrive, 1u);
                    if (o2 == 7) {                      // last column
                        g_arrive = 0;
                        __threadfence();
                        atomicAdd(&g_epoch, 1u);
                    }
                }
                while (((*(volatile unsigned int*)&g_epoch) - e0) < (unsigned int)(t + 1)) { }
                __threadfence();
            }
            __syncthreads();
        }
    }
}

// ---------------------------------------------------------------------------
extern "C" void kernel_launch(void* const* d_in, const int* in_sizes, int n_in,
                              void* d_out, int out_size) {
    const int*           nodes = (const int*)d_in[0];
    const void*          edges = d_in[1];
    const float*         h0    = (const float*)d_in[2];
    const float*         emb   = (const float*)d_in[3];
    const float*         cWih  = (const float*)d_in[4];
    const float*         cWhh  = (const float*)d_in[5];
    const float*         cbih  = (const float*)d_in[6];
    const float*         cbhh  = (const float*)d_in[7];
    const float*         sWih  = (const float*)d_in[8];
    const float*         sWhh  = (const float*)d_in[9];
    const float*         sbih  = (const float*)d_in[10];
    const float*         sbhh  = (const float*)d_in[11];
    float* out = (float*)d_out;

    detect_edges_kernel<<<1, 1>>>((const unsigned char*)edges);
    bucket_kernel<<<1, 256>>>(edges);

    dim3 gP(G3 / 64, VV / 64, 2);
    precompute_P_kernel<<<gP, 256>>>(emb, cWih, cbih, cbhh, sWih, sbih, sbhh);

    static int smem_bytes = (2 * 256 * 96 + 256 * 32) * 4;   // 229376
    cudaFuncSetAttribute(persistent_kernel,
                         cudaFuncAttributeMaxDynamicSharedMemorySize, smem_bytes);
    persistent_kernel<<<dim3(8, 17), 512, smem_bytes>>>(
        h0, out, nodes, cWhh, cbhh, sWhh, sbhh);

    cudaMemcpyAsync(out + (size_t)TT * DH, out + (size_t)(TT - 1) * DH,
                    (size_t)DH * sizeof(float), cudaMemcpyDeviceToDevice, 0);
}